// round 7
// baseline (speedup 1.0000x reference)
#include <cuda_runtime.h>
#include <cuda_bf16.h>
#include <cstdint>

// Problem sizes (fixed).
#define NB  2048
#define DD  1024
#define HH  131072
#define CC  1024
#define SSZ 8192

// ---------------- scratch (device globals; no allocation allowed) -----------
__device__ __nv_bfloat16 g_Xhi[NB * DD];
__device__ __nv_bfloat16 g_Xlo[NB * DD];
__device__ __nv_bfloat16 g_Wghi[SSZ * DD];
__device__ __nv_bfloat16 g_Wglo[SSZ * DD];
__device__ float         g_bg[SSZ];
__device__ __nv_bfloat16 g_Wohi[(size_t)CC * SSZ];
__device__ __nv_bfloat16 g_Wolo[(size_t)CC * SSZ];
__device__ __nv_bfloat16 g_hhi[(size_t)NB * SSZ];
__device__ __nv_bfloat16 g_hlo[(size_t)NB * SSZ];
__device__ int g_ids64;

#define DEVFN __device__ __forceinline__

DEVFN uint32_t smem_u32(const void* p) {
    uint32_t a;
    asm("{ .reg .u64 t; cvta.to.shared.u64 t, %1; cvt.u32.u64 %0, t; }"
        : "=r"(a) : "l"(p));
    return a;
}

DEVFN void split1(float v, __nv_bfloat16& h, __nv_bfloat16& l) {
    h = __float2bfloat16(v);
    l = __float2bfloat16(v - __bfloat162float(h));
}

DEVFN uint32_t pack2(__nv_bfloat16 a, __nv_bfloat16 b) {
    return (uint32_t)__bfloat16_as_ushort(a) | ((uint32_t)__bfloat16_as_ushort(b) << 16);
}

#define SWZ(o) ((o) ^ (((o) >> 3) & 0x70))

DEVFN void cpa16(uint32_t d, const void* g) {
    asm volatile("cp.async.cg.shared.global [%0], [%1], 16;" :: "r"(d), "l"(g));
}

#define LDM4(r, addr) \
    asm volatile("ldmatrix.sync.aligned.m8n8.x4.shared.b16 {%0,%1,%2,%3}, [%4];" \
                 : "=r"((r)[0]), "=r"((r)[1]), "=r"((r)[2]), "=r"((r)[3]) \
                 : "r"(addr))

DEVFN void mma16816(float* c, const uint32_t* a, uint32_t b0, uint32_t b1) {
    asm volatile(
        "mma.sync.aligned.m16n8k16.row.col.f32.bf16.bf16.f32 "
        "{%0,%1,%2,%3}, {%4,%5,%6,%7}, {%8,%9}, {%0,%1,%2,%3};"
        : "+f"(c[0]), "+f"(c[1]), "+f"(c[2]), "+f"(c[3])
        : "r"(a[0]), "r"(a[1]), "r"(a[2]), "r"(a[3]), "r"(b0), "r"(b1));
}

// ---------------- pre-pass kernels -------------------------------------------
__global__ void k_detect(const int* __restrict__ ids32) {
    if (threadIdx.x == 0) {
        int all0 = 1;
        for (int j = 1; j < 128; j += 2) all0 &= (ids32[j] == 0);
        g_ids64 = all0;
    }
}

DEVFN long long load_id(const void* idsp, int s) {
    return g_ids64 ? ((const long long*)idsp)[s] : (long long)((const int*)idsp)[s];
}

__global__ void k_splitX(const float4* __restrict__ X4) {
    int i = blockIdx.x * blockDim.x + threadIdx.x;
    float4 v = X4[i];
    __nv_bfloat16 h0, h1, h2, h3, l0, l1, l2, l3;
    split1(v.x, h0, l0); split1(v.y, h1, l1);
    split1(v.z, h2, l2); split1(v.w, h3, l3);
    ((uint2*)g_Xhi)[i] = make_uint2(pack2(h0, h1), pack2(h2, h3));
    ((uint2*)g_Xlo)[i] = make_uint2(pack2(l0, l1), pack2(l2, l3));
}

__global__ void k_gatherWh(const float* __restrict__ Wh, const float* __restrict__ bh,
                           const void* __restrict__ idsp) {
    int s = blockIdx.x;
    long long id = load_id(idsp, s);
    const float4* src = (const float4*)(Wh + (size_t)id * DD);
    uint2* dh = (uint2*)(g_Wghi + (size_t)s * DD);
    uint2* dl = (uint2*)(g_Wglo + (size_t)s * DD);
    for (int j = threadIdx.x; j < DD / 4; j += blockDim.x) {
        float4 v = src[j];
        __nv_bfloat16 h0, h1, h2, h3, l0, l1, l2, l3;
        split1(v.x, h0, l0); split1(v.y, h1, l1);
        split1(v.z, h2, l2); split1(v.w, h3, l3);
        dh[j] = make_uint2(pack2(h0, h1), pack2(h2, h3));
        dl[j] = make_uint2(pack2(l0, l1), pack2(l2, l3));
    }
    if (threadIdx.x == 0) g_bg[s] = bh[id];
}

__global__ void k_gatherWo(const float* __restrict__ Wo, const void* __restrict__ idsp) {
    int s = blockIdx.x * blockDim.x + threadIdx.x;
    int c = blockIdx.y;
    long long id = load_id(idsp, s);
    float v = Wo[(size_t)c * HH + (size_t)id];
    __nv_bfloat16 h, l;
    split1(v, h, l);
    g_Wohi[(size_t)c * SSZ + s] = h;
    g_Wolo[(size_t)c * SSZ + s] = l;
}

// ---------------- split-bf16 GEMM via mma.sync (HMMA) ------------------------
// C[M,N] = A[M,K]*B[N,K]^T, A=Ahi+Alo, B=Bhi+Blo, D = AhiBhi + AhiBlo + AloBhi.
// CTA tile 128x128, BK=64, double-buffered cp.async, SW128 swizzle, 8 warps
// (4m x 2n, warp tile 32x64), ldmatrix.x4 both operands (K-major, no trans).
// EPI==0: +bias, relu, split -> (outHi,outLo) bf16. EPI==1: +bias -> fp32.

template <int EPI>
__global__ void __launch_bounds__(256, 1) k_gemm(
    const __nv_bfloat16* __restrict__ Ahi, const __nv_bfloat16* __restrict__ Alo,
    const __nv_bfloat16* __restrict__ Bhi, const __nv_bfloat16* __restrict__ Blo,
    const float* __restrict__ bias,
    float* __restrict__ outF,
    __nv_bfloat16* __restrict__ outHi, __nv_bfloat16* __restrict__ outLo,
    int K, int ldo)
{
    extern __shared__ char dsm[];
    __shared__ float s_bias[128];

    const int tid = threadIdx.x;
    const int wid = tid >> 5, lane = tid & 31;
    const int m0 = blockIdx.y * 128;
    const int n0 = blockIdx.x * 128;
    const uint32_t sbase = (smem_u32(dsm) + 1023u) & ~1023u;

    if (tid < 128) s_bias[tid] = bias[n0 + tid];

    const __nv_bfloat16* ga[4] = {
        Ahi + (size_t)m0 * K, Alo + (size_t)m0 * K,
        Bhi + (size_t)n0 * K, Blo + (size_t)n0 * K };
    const int KT = K >> 6;

    auto load_stage = [&](int kt) {
        const uint32_t sb = sbase + (uint32_t)(kt & 1) * 65536u;
        #pragma unroll
        for (int tile = 0; tile < 4; tile++) {
            const __nv_bfloat16* g = ga[tile] + kt * 64;
            const uint32_t tb = sb + (uint32_t)tile * 16384u;
            #pragma unroll
            for (int j = 0; j < 4; j++) {
                int ch = tid + j * 256;
                int row = ch & 127, w = ch >> 7;
                cpa16(tb + SWZ((uint32_t)(row * 128 + w * 16)),
                      g + (size_t)row * K + (size_t)w * 8);
            }
        }
        asm volatile("cp.async.commit_group;" ::: "memory");
    };

    float acc[2][8][4];
    #pragma unroll
    for (int i = 0; i < 2; i++)
        #pragma unroll
        for (int j = 0; j < 8; j++)
            #pragma unroll
            for (int q = 0; q < 4; q++) acc[i][j][q] = 0.0f;

    const int wm = wid >> 1, wn = wid & 1;
    const uint32_t rA = (uint32_t)(wm * 32 + (lane & 15));
    const uint32_t rB = (uint32_t)(wn * 64 + (lane & 15));
    const uint32_t cB = (uint32_t)((lane >> 4) * 16);

    load_stage(0);
    for (int kt = 0; kt < KT; kt++) {
        if (kt + 1 < KT) {
            load_stage(kt + 1);
            asm volatile("cp.async.wait_group 1;" ::: "memory");
        } else {
            asm volatile("cp.async.wait_group 0;" ::: "memory");
        }
        __syncthreads();

        const uint32_t sb  = sbase + (uint32_t)(kt & 1) * 65536u;
        const uint32_t sAh = sb, sAl = sb + 16384u, sBh = sb + 32768u, sBl = sb + 49152u;

        #pragma unroll
        for (int ks = 0; ks < 4; ks++) {
            const uint32_t kb = (uint32_t)(ks * 32) + cB;
            uint32_t ah[2][4], al[2][4];
            #pragma unroll
            for (int mi = 0; mi < 2; mi++) {
                uint32_t off = SWZ((rA + mi * 16) * 128 + kb);
                LDM4(ah[mi], sAh + off);
                LDM4(al[mi], sAl + off);
            }
            #pragma unroll
            for (int nj = 0; nj < 4; nj++) {
                uint32_t bh[4], bl[4];
                uint32_t off = SWZ((rB + nj * 16) * 128 + kb);
                LDM4(bh, sBh + off);
                LDM4(bl, sBl + off);
                #pragma unroll
                for (int mi = 0; mi < 2; mi++) {
                    #pragma unroll
                    for (int p = 0; p < 2; p++) {
                        float* c = acc[mi][nj * 2 + p];
                        mma16816(c, ah[mi], bh[p], bh[p + 2]);
                        mma16816(c, ah[mi], bl[p], bl[p + 2]);
                        mma16816(c, al[mi], bh[p], bh[p + 2]);
                    }
                }
            }
        }
        __syncthreads();
    }

    // Epilogue. c0,c1 -> row (lane>>2), cols 2(lane&3)+{0,1}; c2,c3 -> row+8.
    const int er = lane >> 2;
    const int ec = 2 * (lane & 3);
    #pragma unroll
    for (int mi = 0; mi < 2; mi++) {
        const int row = m0 + wm * 32 + mi * 16 + er;
        #pragma unroll
        for (int nf = 0; nf < 8; nf++) {
            const int colL = wn * 64 + nf * 8 + ec;
            const size_t o0 = (size_t)row * ldo + (size_t)(n0 + colL);
            const size_t o1 = o0 + (size_t)8 * ldo;
            float v0 = acc[mi][nf][0] + s_bias[colL];
            float v1 = acc[mi][nf][1] + s_bias[colL + 1];
            float v2 = acc[mi][nf][2] + s_bias[colL];
            float v3 = acc[mi][nf][3] + s_bias[colL + 1];
            if constexpr (EPI == 0) {
                v0 = fmaxf(v0, 0.0f); v1 = fmaxf(v1, 0.0f);
                v2 = fmaxf(v2, 0.0f); v3 = fmaxf(v3, 0.0f);
                __nv_bfloat16 h0, h1, h2, h3, e0, e1, e2, e3;
                split1(v0, h0, e0); split1(v1, h1, e1);
                split1(v2, h2, e2); split1(v3, h3, e3);
                *(uint32_t*)(outHi + o0) = pack2(h0, h1);
                *(uint32_t*)(outLo + o0) = pack2(e0, e1);
                *(uint32_t*)(outHi + o1) = pack2(h2, h3);
                *(uint32_t*)(outLo + o1) = pack2(e2, e3);
            } else {
                *(float2*)(outF + o0) = make_float2(v0, v1);
                *(float2*)(outF + o1) = make_float2(v2, v3);
            }
        }
    }
}

// ---------------- launch -----------------------------------------------------
extern "C" void kernel_launch(void* const* d_in, const int* in_sizes, int n_in,
                              void* d_out, int out_size) {
    const float* X   = (const float*)d_in[0];
    const float* Wh  = (const float*)d_in[1];
    const float* bh  = (const float*)d_in[2];
    const float* Wo  = (const float*)d_in[3];
    const float* bo  = (const float*)d_in[4];
    const void*  ids = d_in[5];
    float* out = (float*)d_out;
    (void)in_sizes; (void)n_in; (void)out_size;

    void *pXhi, *pXlo, *pWghi, *pWglo, *pbg, *pWohi, *pWolo, *phhi, *phlo;
    cudaGetSymbolAddress(&pXhi, g_Xhi);   cudaGetSymbolAddress(&pXlo, g_Xlo);
    cudaGetSymbolAddress(&pWghi, g_Wghi); cudaGetSymbolAddress(&pWglo, g_Wglo);
    cudaGetSymbolAddress(&pbg, g_bg);
    cudaGetSymbolAddress(&pWohi, g_Wohi); cudaGetSymbolAddress(&pWolo, g_Wolo);
    cudaGetSymbolAddress(&phhi, g_hhi);   cudaGetSymbolAddress(&phlo, g_hlo);

    const int smem = 2 * 65536 + 1024;  // 132 KB: 2 stages x 4 tiles x 16 KB
    cudaFuncSetAttribute(k_gemm<0>, cudaFuncAttributeMaxDynamicSharedMemorySize, smem);
    cudaFuncSetAttribute(k_gemm<1>, cudaFuncAttributeMaxDynamicSharedMemorySize, smem);

    k_detect<<<1, 32>>>((const int*)ids);
    k_splitX<<<(NB * DD / 4) / 256, 256>>>((const float4*)X);
    k_gatherWh<<<SSZ, 128>>>(Wh, bh, ids);
    k_gatherWo<<<dim3(SSZ / 256, CC), 256>>>(Wo, ids);

    // GEMM1: h = relu(X * Wg^T + bg) -> bf16 hi/lo. M=2048, N=8192, K=1024.
    k_gemm<0><<<dim3(SSZ / 128, NB / 128), 256, smem>>>(
        (const __nv_bfloat16*)pXhi, (const __nv_bfloat16*)pXlo,
        (const __nv_bfloat16*)pWghi, (const __nv_bfloat16*)pWglo,
        (const float*)pbg, nullptr,
        (__nv_bfloat16*)phhi, (__nv_bfloat16*)phlo,
        DD, SSZ);

    // GEMM2: out = h * WoT^T + b_out (fp32). M=2048, N=1024, K=8192.
    k_gemm<1><<<dim3(CC / 128, NB / 128), 256, smem>>>(
        (const __nv_bfloat16*)phhi, (const __nv_bfloat16*)phlo,
        (const __nv_bfloat16*)pWohi, (const __nv_bfloat16*)pWolo,
        bo, out, nullptr, nullptr,
        SSZ, CC);
}

// round 9
// speedup vs baseline: 1.3621x; 1.3621x over previous
#include <cuda_runtime.h>
#include <cuda_bf16.h>
#include <cstdint>

// Problem sizes (fixed).
#define NB  2048
#define DD  1024
#define HH  131072
#define CC  1024
#define SSZ 8192

// ---------------- scratch (device globals; no allocation allowed) -----------
__device__ __nv_bfloat16 g_Xhi[NB * DD];
__device__ __nv_bfloat16 g_Xlo[NB * DD];
__device__ __nv_bfloat16 g_Wghi[SSZ * DD];
__device__ __nv_bfloat16 g_Wglo[SSZ * DD];
__device__ float         g_bg[SSZ];
__device__ __nv_bfloat16 g_Wohi[(size_t)CC * SSZ];
__device__ __nv_bfloat16 g_Wolo[(size_t)CC * SSZ];
__device__ __nv_bfloat16 g_hhi[(size_t)NB * SSZ];
__device__ __nv_bfloat16 g_hlo[(size_t)NB * SSZ];
__device__ int g_ids64;

#define DEVFN __device__ __forceinline__

DEVFN uint32_t smem_u32(const void* p) {
    uint32_t a;
    asm("{ .reg .u64 t; cvta.to.shared.u64 t, %1; cvt.u32.u64 %0, t; }"
        : "=r"(a) : "l"(p));
    return a;
}

DEVFN void split1(float v, __nv_bfloat16& h, __nv_bfloat16& l) {
    h = __float2bfloat16(v);
    l = __float2bfloat16(v - __bfloat162float(h));
}

DEVFN uint32_t pack2(__nv_bfloat16 a, __nv_bfloat16 b) {
    return (uint32_t)__bfloat16_as_ushort(a) | ((uint32_t)__bfloat16_as_ushort(b) << 16);
}

// SW64 swizzle for 64-byte rows: XOR 16B-chunk bits [5:4] with row bits [8:7].
#define SWZ64(o) ((uint32_t)(o) ^ ((((uint32_t)(o)) >> 3) & 0x30u))

#define LDM4(r, addr) \
    asm volatile("ldmatrix.sync.aligned.m8n8.x4.shared.b16 {%0,%1,%2,%3}, [%4];" \
                 : "=r"((r)[0]), "=r"((r)[1]), "=r"((r)[2]), "=r"((r)[3]) \
                 : "r"(addr))

#define STS16(addr, v) \
    asm volatile("st.shared.v4.b32 [%0], {%1,%2,%3,%4};" \
                 :: "r"(addr), "r"((v).x), "r"((v).y), "r"((v).z), "r"((v).w))

DEVFN void mma16816(float* c, const uint32_t* a, uint32_t b0, uint32_t b1) {
    asm volatile(
        "mma.sync.aligned.m16n8k16.row.col.f32.bf16.bf16.f32 "
        "{%0,%1,%2,%3}, {%4,%5,%6,%7}, {%8,%9}, {%0,%1,%2,%3};"
        : "+f"(c[0]), "+f"(c[1]), "+f"(c[2]), "+f"(c[3])
        : "r"(a[0]), "r"(a[1]), "r"(a[2]), "r"(a[3]), "r"(b0), "r"(b1));
}

// ---------------- pre-pass kernels -------------------------------------------
__global__ void k_detect(const int* __restrict__ ids32) {
    if (threadIdx.x == 0) {
        int all0 = 1;
        for (int j = 1; j < 128; j += 2) all0 &= (ids32[j] == 0);
        g_ids64 = all0;
    }
}

DEVFN long long load_id(const void* idsp, int s) {
    return g_ids64 ? ((const long long*)idsp)[s] : (long long)((const int*)idsp)[s];
}

__global__ void k_splitX(const float4* __restrict__ X4) {
    int i = blockIdx.x * blockDim.x + threadIdx.x;
    float4 v = X4[i];
    __nv_bfloat16 h0, h1, h2, h3, l0, l1, l2, l3;
    split1(v.x, h0, l0); split1(v.y, h1, l1);
    split1(v.z, h2, l2); split1(v.w, h3, l3);
    ((uint2*)g_Xhi)[i] = make_uint2(pack2(h0, h1), pack2(h2, h3));
    ((uint2*)g_Xlo)[i] = make_uint2(pack2(l0, l1), pack2(l2, l3));
}

__global__ void k_gatherWh(const float* __restrict__ Wh, const float* __restrict__ bh,
                           const void* __restrict__ idsp) {
    int s = blockIdx.x;
    long long id = load_id(idsp, s);
    const float4* src = (const float4*)(Wh + (size_t)id * DD);
    uint2* dh = (uint2*)(g_Wghi + (size_t)s * DD);
    uint2* dl = (uint2*)(g_Wglo + (size_t)s * DD);
    for (int j = threadIdx.x; j < DD / 4; j += blockDim.x) {
        float4 v = src[j];
        __nv_bfloat16 h0, h1, h2, h3, l0, l1, l2, l3;
        split1(v.x, h0, l0); split1(v.y, h1, l1);
        split1(v.z, h2, l2); split1(v.w, h3, l3);
        dh[j] = make_uint2(pack2(h0, h1), pack2(h2, h3));
        dl[j] = make_uint2(pack2(l0, l1), pack2(l2, l3));
    }
    if (threadIdx.x == 0) g_bg[s] = bh[id];
}

__global__ void k_gatherWo(const float* __restrict__ Wo, const void* __restrict__ idsp) {
    int s = blockIdx.x * blockDim.x + threadIdx.x;
    int c = blockIdx.y;
    long long id = load_id(idsp, s);
    float v = Wo[(size_t)c * HH + (size_t)id];
    __nv_bfloat16 h, l;
    split1(v, h, l);
    g_Wohi[(size_t)c * SSZ + s] = h;
    g_Wolo[(size_t)c * SSZ + s] = l;
}

// ---------------- split-bf16 GEMM via mma.sync (HMMA) ------------------------
// C[M,N] = A[M,K]*B[N,K]^T, A=Ahi+Alo, B=Bhi+Blo, D = AhiBhi + AhiBlo + AloBhi.
// CTA tile 128 x TN, BK=32, SW64-swizzled smem, double buffer, LDG.128->STS.128
// pipelined fill, 8 warps (4m x 2n), ldmatrix.x4 both operands (K-major).
// 2 CTAs/SM. EPI==0: +bias,relu,split -> bf16 hi/lo. EPI==1: +bias -> fp32.

template <int TN, int EPI>
__global__ void __launch_bounds__(256, 2) k_gemm(
    const __nv_bfloat16* __restrict__ Ahi, const __nv_bfloat16* __restrict__ Alo,
    const __nv_bfloat16* __restrict__ Bhi, const __nv_bfloat16* __restrict__ Blo,
    const float* __restrict__ bias,
    float* __restrict__ outF,
    __nv_bfloat16* __restrict__ outHi, __nv_bfloat16* __restrict__ outLo,
    int K, int ldo)
{
    constexpr int NJ = TN / 32;                 // ldmatrix n16 frags per warp
    constexpr int NF = TN / 16;                 // n8 accum frags per warp
    constexpr int NCB = TN / 64;                // B 16B-chunks per thread per tile
    constexpr uint32_t ASZ = 128 * 64;          // 8 KB per A tile (128 rows x 64B)
    constexpr uint32_t BSZ = (uint32_t)TN * 64;
    constexpr uint32_t STG = 2 * ASZ + 2 * BSZ;

    extern __shared__ char dsm[];
    __shared__ float s_bias[TN];

    const int tid = threadIdx.x;
    const int wid = tid >> 5, lane = tid & 31;
    const int m0 = blockIdx.y * 128;
    const int n0 = blockIdx.x * TN;
    const uint32_t sbase = (smem_u32(dsm) + 1023u) & ~1023u;

    for (int j = tid; j < TN; j += 256) s_bias[j] = bias[n0 + j];

    // ---- fill descriptors: chunk c -> row c>>2, 16B-word c&3 (coalesced) ----
    const ptrdiff_t dA = Alo - Ahi;   // uniform hi->lo delta
    const ptrdiff_t dB = Blo - Bhi;
    uint32_t asoff[2];
    const __nv_bfloat16* pA[2];
    #pragma unroll
    for (int j = 0; j < 2; j++) {
        int c = tid + j * 256, row = c >> 2, wi = c & 3;
        asoff[j] = SWZ64(row * 64 + wi * 16);
        pA[j] = Ahi + (size_t)(m0 + row) * K + wi * 8;
    }
    uint32_t bsoff[NCB];
    const __nv_bfloat16* pB[NCB];
    #pragma unroll
    for (int j = 0; j < NCB; j++) {
        int c = tid + j * 256, row = c >> 2, wi = c & 3;
        bsoff[j] = SWZ64(row * 64 + wi * 16);
        pB[j] = Bhi + (size_t)(n0 + row) * K + wi * 8;
    }

    // ---- ldmatrix offsets (loop-invariant, swizzled) ----
    const int wm = wid >> 1, wn = wid & 1;
    const int rA = wm * 32 + (lane & 15);
    const int rB = wn * (TN / 2) + (lane & 15);
    const int kb = (lane >> 4) * 16;
    uint32_t aoff[2][2], boff[NJ][2];
    #pragma unroll
    for (int mi = 0; mi < 2; mi++)
        #pragma unroll
        for (int ks = 0; ks < 2; ks++)
            aoff[mi][ks] = SWZ64((rA + mi * 16) * 64 + ks * 32 + kb);
    #pragma unroll
    for (int nj = 0; nj < NJ; nj++)
        #pragma unroll
        for (int ks = 0; ks < 2; ks++)
            boff[nj][ks] = SWZ64((rB + nj * 16) * 64 + ks * 32 + kb);

    float acc[2][NF][4];
    #pragma unroll
    for (int i = 0; i < 2; i++)
        #pragma unroll
        for (int j = 0; j < NF; j++)
            #pragma unroll
            for (int q = 0; q < 4; q++) acc[i][j][q] = 0.0f;

    uint4 sAh[2], sAl[2], sBh[NCB], sBl[NCB];

    auto ldg = [&](int kt) {
        const size_t off = (size_t)kt * 32;
        #pragma unroll
        for (int j = 0; j < 2; j++) {
            sAh[j] = *(const uint4*)(pA[j] + off);
            sAl[j] = *(const uint4*)(pA[j] + dA + off);
        }
        #pragma unroll
        for (int j = 0; j < NCB; j++) {
            sBh[j] = *(const uint4*)(pB[j] + off);
            sBl[j] = *(const uint4*)(pB[j] + dB + off);
        }
    };
    auto sts = [&](int b) {
        const uint32_t s0 = sbase + (uint32_t)b * STG;
        #pragma unroll
        for (int j = 0; j < 2; j++) {
            STS16(s0 + asoff[j], sAh[j]);
            STS16(s0 + ASZ + asoff[j], sAl[j]);
        }
        #pragma unroll
        for (int j = 0; j < NCB; j++) {
            STS16(s0 + 2 * ASZ + bsoff[j], sBh[j]);
            STS16(s0 + 2 * ASZ + BSZ + bsoff[j], sBl[j]);
        }
    };

    const int KT = K >> 5;
    ldg(0);
    sts(0);
    __syncthreads();

    for (int kt = 0; kt < KT; kt++) {
        const bool more = (kt + 1 < KT);
        if (more) ldg(kt + 1);              // LDG overlapped with mma below

        const uint32_t s0  = sbase + (uint32_t)(kt & 1) * STG;
        const uint32_t tAh = s0, tAl = s0 + ASZ;
        const uint32_t tBh = s0 + 2 * ASZ, tBl = s0 + 2 * ASZ + BSZ;

        #pragma unroll
        for (int ks = 0; ks < 2; ks++) {
            uint32_t ah[2][4], al[2][4];
            #pragma unroll
            for (int mi = 0; mi < 2; mi++) {
                LDM4(ah[mi], tAh + aoff[mi][ks]);
                LDM4(al[mi], tAl + aoff[mi][ks]);
            }
            #pragma unroll
            for (int nj = 0; nj < NJ; nj++) {
                uint32_t bh[4], bl[4];
                LDM4(bh, tBh + boff[nj][ks]);
                LDM4(bl, tBl + boff[nj][ks]);
                #pragma unroll
                for (int mi = 0; mi < 2; mi++) {
                    #pragma unroll
                    for (int p = 0; p < 2; p++) {
                        float* c = acc[mi][nj * 2 + p];
                        mma16816(c, ah[mi], bh[p], bh[p + 2]);
                        mma16816(c, ah[mi], bl[p], bl[p + 2]);
                        mma16816(c, al[mi], bh[p], bh[p + 2]);
                    }
                }
            }
        }
        if (more) sts((kt + 1) & 1);
        __syncthreads();
    }

    // ---- epilogue: c0,c1 -> row lane>>2, cols 2(lane&3)+{0,1}; c2,c3 -> +8 ----
    const int er = lane >> 2;
    const int ec = 2 * (lane & 3);
    #pragma unroll
    for (int mi = 0; mi < 2; mi++) {
        const int row = m0 + wm * 32 + mi * 16 + er;
        #pragma unroll
        for (int nf = 0; nf < NF; nf++) {
            const int colL = wn * (TN / 2) + nf * 8 + ec;
            const size_t o0 = (size_t)row * ldo + (size_t)(n0 + colL);
            const size_t o1 = o0 + (size_t)8 * ldo;
            float v0 = acc[mi][nf][0] + s_bias[colL];
            float v1 = acc[mi][nf][1] + s_bias[colL + 1];
            float v2 = acc[mi][nf][2] + s_bias[colL];
            float v3 = acc[mi][nf][3] + s_bias[colL + 1];
            if constexpr (EPI == 0) {
                v0 = fmaxf(v0, 0.0f); v1 = fmaxf(v1, 0.0f);
                v2 = fmaxf(v2, 0.0f); v3 = fmaxf(v3, 0.0f);
                __nv_bfloat16 h0, h1, h2, h3, e0, e1, e2, e3;
                split1(v0, h0, e0); split1(v1, h1, e1);
                split1(v2, h2, e2); split1(v3, h3, e3);
                *(uint32_t*)(outHi + o0) = pack2(h0, h1);
                *(uint32_t*)(outLo + o0) = pack2(e0, e1);
                *(uint32_t*)(outHi + o1) = pack2(h2, h3);
                *(uint32_t*)(outLo + o1) = pack2(e2, e3);
            } else {
                *(float2*)(outF + o0) = make_float2(v0, v1);
                *(float2*)(outF + o1) = make_float2(v2, v3);
            }
        }
    }
}

// ---------------- launch -----------------------------------------------------
extern "C" void kernel_launch(void* const* d_in, const int* in_sizes, int n_in,
                              void* d_out, int out_size) {
    const float* X   = (const float*)d_in[0];
    const float* Wh  = (const float*)d_in[1];
    const float* bh  = (const float*)d_in[2];
    const float* Wo  = (const float*)d_in[3];
    const float* bo  = (const float*)d_in[4];
    const void*  ids = d_in[5];
    float* out = (float*)d_out;
    (void)in_sizes; (void)n_in; (void)out_size;

    void *pXhi, *pXlo, *pWghi, *pWglo, *pbg, *pWohi, *pWolo, *phhi, *phlo;
    cudaGetSymbolAddress(&pXhi, g_Xhi);   cudaGetSymbolAddress(&pXlo, g_Xlo);
    cudaGetSymbolAddress(&pWghi, g_Wghi); cudaGetSymbolAddress(&pWglo, g_Wglo);
    cudaGetSymbolAddress(&pbg, g_bg);
    cudaGetSymbolAddress(&pWohi, g_Wohi); cudaGetSymbolAddress(&pWolo, g_Wolo);
    cudaGetSymbolAddress(&phhi, g_hhi);   cudaGetSymbolAddress(&phlo, g_hlo);

    // smem: 2 stages; stage = 2*8KB (A) + 2*TN*64B (B). +1KB alignment pad.
    const int smem1 = 2 * (2 * 8192 + 2 * 128 * 64) + 1024;  // 66560
    const int smem2 = 2 * (2 * 8192 + 2 * 64 * 64) + 1024;   // 50176
    cudaFuncSetAttribute(k_gemm<128, 0>, cudaFuncAttributeMaxDynamicSharedMemorySize, smem1);
    cudaFuncSetAttribute(k_gemm<64, 1>,  cudaFuncAttributeMaxDynamicSharedMemorySize, smem2);

    k_detect<<<1, 32>>>((const int*)ids);
    k_splitX<<<(NB * DD / 4) / 256, 256>>>((const float4*)X);
    k_gatherWh<<<SSZ, 128>>>(Wh, bh, ids);
    k_gatherWo<<<dim3(SSZ / 256, CC), 256>>>(Wo, ids);

    // GEMM1: h = relu(X * Wg^T + bg) -> bf16 hi/lo. M=2048, N=8192, K=1024.
    k_gemm<128, 0><<<dim3(SSZ / 128, NB / 128), 256, smem1>>>(
        (const __nv_bfloat16*)pXhi, (const __nv_bfloat16*)pXlo,
        (const __nv_bfloat16*)pWghi, (const __nv_bfloat16*)pWglo,
        (const float*)pbg, nullptr,
        (__nv_bfloat16*)phhi, (__nv_bfloat16*)phlo,
        DD, SSZ);

    // GEMM2: out = h * WoT^T + b_out (fp32). M=2048, N=1024, K=8192.
    k_gemm<64, 1><<<dim3(CC / 64, NB / 128), 256, smem2>>>(
        (const __nv_bfloat16*)phhi, (const __nv_bfloat16*)phlo,
        (const __nv_bfloat16*)pWohi, (const __nv_bfloat16*)pWolo,
        bo, out, nullptr, nullptr,
        SSZ, CC);
}

// round 10
// speedup vs baseline: 1.6295x; 1.1963x over previous
#include <cuda_runtime.h>
#include <cuda_bf16.h>
#include <cstdint>

// Problem sizes (fixed).
#define NB  2048
#define DD  1024
#define HH  131072
#define CC  1024
#define SSZ 8192

// ---------------- scratch (device globals; no allocation allowed) -----------
__device__ float g_Xt[NB * DD];                // X, tf32-rounded
__device__ float g_Wgt[SSZ * DD];              // gathered W_hidden rows, tf32
__device__ float g_bg[SSZ];                    // gathered b_hidden (exact fp32)
__device__ float g_Wot[(size_t)CC * SSZ];      // gathered W_out cols, tf32
__device__ float g_h[(size_t)NB * SSZ];        // relu hidden, tf32-rounded
__device__ int g_ids64;

#define DEVFN __device__ __forceinline__

DEVFN uint32_t smem_u32(const void* p) {
    uint32_t a;
    asm("{ .reg .u64 t; cvta.to.shared.u64 t, %1; cvt.u32.u64 %0, t; }"
        : "=r"(a) : "l"(p));
    return a;
}

// Round-to-nearest tf32 (unbiased). REQUIRED: letting the MMA truncate fp32
// operands adds a coherent ~2^-10 bias that accumulates over K.
DEVFN float totf(float x) {
    float r;
    asm("cvt.rna.tf32.f32 %0, %1;" : "=f"(r) : "f"(x));
    return r;
}

// SW64 swizzle for 64-byte rows: XOR 16B-chunk bits [5:4] with row bits [8:7].
#define SWZ64(o) ((uint32_t)(o) ^ ((((uint32_t)(o)) >> 3) & 0x30u))

#define LDM4(r, addr) \
    asm volatile("ldmatrix.sync.aligned.m8n8.x4.shared.b16 {%0,%1,%2,%3}, [%4];" \
                 : "=r"((r)[0]), "=r"((r)[1]), "=r"((r)[2]), "=r"((r)[3]) \
                 : "r"(addr))

#define STS16(addr, v) \
    asm volatile("st.shared.v4.b32 [%0], {%1,%2,%3,%4};" \
                 :: "r"(addr), "r"((v).x), "r"((v).y), "r"((v).z), "r"((v).w))

DEVFN void mma1688(float* c, const uint32_t* a, uint32_t b0, uint32_t b1) {
    asm volatile(
        "mma.sync.aligned.m16n8k8.row.col.f32.tf32.tf32.f32 "
        "{%0,%1,%2,%3}, {%4,%5,%6,%7}, {%8,%9}, {%0,%1,%2,%3};"
        : "+f"(c[0]), "+f"(c[1]), "+f"(c[2]), "+f"(c[3])
        : "r"(a[0]), "r"(a[1]), "r"(a[2]), "r"(a[3]), "r"(b0), "r"(b1));
}

// ---------------- pre-pass kernels -------------------------------------------
__global__ void k_detect(const int* __restrict__ ids32) {
    if (threadIdx.x == 0) {
        int all0 = 1;
        for (int j = 1; j < 128; j += 2) all0 &= (ids32[j] == 0);
        g_ids64 = all0;
    }
}

DEVFN long long load_id(const void* idsp, int s) {
    return g_ids64 ? ((const long long*)idsp)[s] : (long long)((const int*)idsp)[s];
}

__global__ void k_cvtX(const float4* __restrict__ X4) {
    int i = blockIdx.x * blockDim.x + threadIdx.x;
    float4 v = X4[i];
    ((float4*)g_Xt)[i] = make_float4(totf(v.x), totf(v.y), totf(v.z), totf(v.w));
}

__global__ void k_gatherWh(const float* __restrict__ Wh, const float* __restrict__ bh,
                           const void* __restrict__ idsp) {
    int s = blockIdx.x;
    long long id = load_id(idsp, s);
    const float4* src = (const float4*)(Wh + (size_t)id * DD);
    float4* dst = (float4*)(g_Wgt + (size_t)s * DD);
    for (int j = threadIdx.x; j < DD / 4; j += blockDim.x) {
        float4 v = src[j];
        dst[j] = make_float4(totf(v.x), totf(v.y), totf(v.z), totf(v.w));
    }
    if (threadIdx.x == 0) g_bg[s] = bh[id];
}

__global__ void k_gatherWo(const float* __restrict__ Wo, const void* __restrict__ idsp) {
    int s = blockIdx.x * blockDim.x + threadIdx.x;
    int c = blockIdx.y;
    long long id = load_id(idsp, s);
    g_Wot[(size_t)c * SSZ + s] = totf(Wo[(size_t)c * HH + (size_t)id]);
}

// ---------------- tf32 GEMM via mma.sync -------------------------------------
// C[M,N] = A[M,K]*B[N,K]^T, fp32 data pre-rounded to tf32 (rna). One MMA term.
// CTA tile 128 x TN, BK=16 tf32 (64B rows), SW64 swizzle, double buffer,
// LDG.128 -> register -> STS.128 pipelined fill, 8 warps (4m x 2n),
// ldmatrix.x4.b16 delivers tf32 fragments (tf32 = b16 pair view).
// EPI==0: +bias, relu, tf32-round -> outH fp32. EPI==1: +bias -> outF fp32.

template <int TN, int EPI>
__global__ void __launch_bounds__(256, 2) k_gemm(
    const float* __restrict__ A, const float* __restrict__ B,
    const float* __restrict__ bias,
    float* __restrict__ outF, float* __restrict__ outH,
    int K, int ldo)
{
    constexpr int NJ  = TN / 32;                // x4 B-loads per kstep (n16 each)
    constexpr int NF  = TN / 16;                // n8 accum frags per warp
    constexpr int NCB = TN / 64;                // B 16B-chunks per thread
    constexpr uint32_t ASZ = 128 * 64;          // 8 KB A tile (128 rows x 64B)
    constexpr uint32_t BSZ = (uint32_t)TN * 64;
    constexpr uint32_t STG = ASZ + BSZ;

    extern __shared__ char dsm[];
    __shared__ float s_bias[TN];

    const int tid = threadIdx.x;
    const int wid = tid >> 5, lane = tid & 31;
    const int m0 = blockIdx.y * 128;
    const int n0 = blockIdx.x * TN;
    const uint32_t sbase = (smem_u32(dsm) + 1023u) & ~1023u;

    for (int j = tid; j < TN; j += 256) s_bias[j] = bias[n0 + j];

    // ---- fill descriptors: chunk c -> row c>>2, 16B-word c&3 (coalesced) ----
    uint32_t asoff[2];
    const float* pA[2];
    #pragma unroll
    for (int j = 0; j < 2; j++) {
        int c = tid + j * 256, row = c >> 2, wi = c & 3;
        asoff[j] = SWZ64(row * 64 + wi * 16);
        pA[j] = A + (size_t)(m0 + row) * K + wi * 4;
    }
    uint32_t bsoff[NCB];
    const float* pB[NCB];
    #pragma unroll
    for (int j = 0; j < NCB; j++) {
        int c = tid + j * 256, row = c >> 2, wi = c & 3;
        bsoff[j] = SWZ64(row * 64 + wi * 16);
        pB[j] = B + (size_t)(n0 + row) * K + wi * 4;
    }

    // ---- ldmatrix offsets (loop-invariant, swizzled) ----
    const int wm = wid >> 1, wn = wid & 1;
    const int rA = wm * 32 + (lane & 15);
    const int rB = wn * (TN / 2) + (lane & 15);
    const int kb = (lane >> 4) * 16;
    uint32_t aoff[2][2], boff[NJ][2];
    #pragma unroll
    for (int mi = 0; mi < 2; mi++)
        #pragma unroll
        for (int ks = 0; ks < 2; ks++)
            aoff[mi][ks] = SWZ64((rA + mi * 16) * 64 + ks * 32 + kb);
    #pragma unroll
    for (int nj = 0; nj < NJ; nj++)
        #pragma unroll
        for (int ks = 0; ks < 2; ks++)
            boff[nj][ks] = SWZ64((rB + nj * 16) * 64 + ks * 32 + kb);

    float acc[2][NF][4];
    #pragma unroll
    for (int i = 0; i < 2; i++)
        #pragma unroll
        for (int j = 0; j < NF; j++)
            #pragma unroll
            for (int q = 0; q < 4; q++) acc[i][j][q] = 0.0f;

    uint4 sA[2], sB[NCB];

    auto ldg = [&](int kt) {
        const size_t off = (size_t)kt * 16;     // BK = 16 tf32
        #pragma unroll
        for (int j = 0; j < 2; j++) sA[j] = *(const uint4*)(pA[j] + off);
        #pragma unroll
        for (int j = 0; j < NCB; j++) sB[j] = *(const uint4*)(pB[j] + off);
    };
    auto sts = [&](int b) {
        const uint32_t s0 = sbase + (uint32_t)b * STG;
        #pragma unroll
        for (int j = 0; j < 2; j++) STS16(s0 + asoff[j], sA[j]);
        #pragma unroll
        for (int j = 0; j < NCB; j++) STS16(s0 + ASZ + bsoff[j], sB[j]);
    };

    const int KT = K >> 4;
    ldg(0);
    sts(0);
    __syncthreads();

    for (int kt = 0; kt < KT; kt++) {
        const bool more = (kt + 1 < KT);
        if (more) ldg(kt + 1);                  // LDG overlapped with mma below

        const uint32_t s0 = sbase + (uint32_t)(kt & 1) * STG;
        const uint32_t tA = s0, tB = s0 + ASZ;

        #pragma unroll
        for (int ks = 0; ks < 2; ks++) {        // k8 per kstep
            uint32_t a[2][4];
            #pragma unroll
            for (int mi = 0; mi < 2; mi++) LDM4(a[mi], tA + aoff[mi][ks]);
            #pragma unroll
            for (int nj = 0; nj < NJ; nj++) {
                uint32_t bb[4];                 // r0/r1 = b0 of n8-frag 0/1, r2/r3 = b1
                LDM4(bb, tB + boff[nj][ks]);
                #pragma unroll
                for (int mi = 0; mi < 2; mi++) {
                    #pragma unroll
                    for (int p = 0; p < 2; p++)
                        mma1688(acc[mi][nj * 2 + p], a[mi], bb[p], bb[p + 2]);
                }
            }
        }
        if (more) sts((kt + 1) & 1);
        __syncthreads();
    }

    // ---- epilogue: c0,c1 -> row lane>>2, cols 2(lane&3)+{0,1}; c2,c3 -> +8 ----
    const int er = lane >> 2;
    const int ec = 2 * (lane & 3);
    #pragma unroll
    for (int mi = 0; mi < 2; mi++) {
        const int row = m0 + wm * 32 + mi * 16 + er;
        #pragma unroll
        for (int nf = 0; nf < NF; nf++) {
            const int colL = wn * (TN / 2) + nf * 8 + ec;
            const size_t o0 = (size_t)row * ldo + (size_t)(n0 + colL);
            const size_t o1 = o0 + (size_t)8 * ldo;
            float v0 = acc[mi][nf][0] + s_bias[colL];
            float v1 = acc[mi][nf][1] + s_bias[colL + 1];
            float v2 = acc[mi][nf][2] + s_bias[colL];
            float v3 = acc[mi][nf][3] + s_bias[colL + 1];
            if constexpr (EPI == 0) {
                *(float2*)(outH + o0) =
                    make_float2(totf(fmaxf(v0, 0.0f)), totf(fmaxf(v1, 0.0f)));
                *(float2*)(outH + o1) =
                    make_float2(totf(fmaxf(v2, 0.0f)), totf(fmaxf(v3, 0.0f)));
            } else {
                *(float2*)(outF + o0) = make_float2(v0, v1);
                *(float2*)(outF + o1) = make_float2(v2, v3);
            }
        }
    }
}

// ---------------- launch -----------------------------------------------------
extern "C" void kernel_launch(void* const* d_in, const int* in_sizes, int n_in,
                              void* d_out, int out_size) {
    const float* X   = (const float*)d_in[0];
    const float* Wh  = (const float*)d_in[1];
    const float* bh  = (const float*)d_in[2];
    const float* Wo  = (const float*)d_in[3];
    const float* bo  = (const float*)d_in[4];
    const void*  ids = d_in[5];
    float* out = (float*)d_out;
    (void)in_sizes; (void)n_in; (void)out_size;

    void *pXt, *pWgt, *pbg, *pWot, *ph;
    cudaGetSymbolAddress(&pXt, g_Xt);
    cudaGetSymbolAddress(&pWgt, g_Wgt);
    cudaGetSymbolAddress(&pbg, g_bg);
    cudaGetSymbolAddress(&pWot, g_Wot);
    cudaGetSymbolAddress(&ph, g_h);

    // smem: 2 stages; stage = 8KB (A) + TN*64B (B). +1KB alignment pad.
    const int smem1 = 2 * (8192 + 128 * 64) + 1024;  // 33792
    const int smem2 = 2 * (8192 + 64 * 64) + 1024;   // 25600
    cudaFuncSetAttribute(k_gemm<128, 0>, cudaFuncAttributeMaxDynamicSharedMemorySize, smem1);
    cudaFuncSetAttribute(k_gemm<64, 1>,  cudaFuncAttributeMaxDynamicSharedMemorySize, smem2);

    k_detect<<<1, 32>>>((const int*)ids);
    k_cvtX<<<(NB * DD / 4) / 256, 256>>>((const float4*)X);
    k_gatherWh<<<SSZ, 128>>>(Wh, bh, ids);
    k_gatherWo<<<dim3(SSZ / 256, CC), 256>>>(Wo, ids);

    // GEMM1: h = tf32(relu(X * Wg^T + bg)). M=2048, N=8192, K=1024.
    k_gemm<128, 0><<<dim3(SSZ / 128, NB / 128), 256, smem1>>>(
        (const float*)pXt, (const float*)pWgt, (const float*)pbg,
        nullptr, (float*)ph, DD, SSZ);

    // GEMM2: out = h * WoT^T + b_out (fp32). M=2048, N=1024, K=8192.
    k_gemm<64, 1><<<dim3(CC / 64, NB / 128), 256, smem2>>>(
        (const float*)ph, (const float*)pWot, bo,
        out, nullptr, SSZ, CC);
}

// round 11
// speedup vs baseline: 1.6542x; 1.0151x over previous
#include <cuda_runtime.h>
#include <cuda_bf16.h>
#include <cstdint>

// Problem sizes (fixed).
#define NB  2048
#define DD  1024
#define HH  131072
#define CC  1024
#define SSZ 8192

// ---------------- scratch (device globals; no allocation allowed) -----------
__device__ float g_Xt[NB * DD];                // X, tf32-rounded
__device__ float g_Wgt[SSZ * DD];              // gathered W_hidden rows, tf32
__device__ float g_bg[SSZ];                    // gathered b_hidden (exact fp32)
__device__ float g_Wot[(size_t)CC * SSZ];      // gathered W_out cols, tf32
__device__ float g_h[(size_t)NB * SSZ];        // relu hidden, tf32-rounded
__device__ int g_ids64;

#define DEVFN __device__ __forceinline__

DEVFN uint32_t smem_u32(const void* p) {
    uint32_t a;
    asm("{ .reg .u64 t; cvta.to.shared.u64 t, %1; cvt.u32.u64 %0, t; }"
        : "=r"(a) : "l"(p));
    return a;
}

// Round-to-nearest tf32 (unbiased). REQUIRED: letting the MMA truncate fp32
// operands adds a coherent ~2^-10 bias that accumulates over K.
DEVFN float totf(float x) {
    float r;
    asm("cvt.rna.tf32.f32 %0, %1;" : "=f"(r) : "f"(x));
    return r;
}

// SW64 swizzle for 64-byte rows: XOR 16B-chunk bits [5:4] with row bits [8:7].
#define SWZ64(o) ((uint32_t)(o) ^ ((((uint32_t)(o)) >> 3) & 0x30u))

#define LDM4(r, addr) \
    asm volatile("ldmatrix.sync.aligned.m8n8.x4.shared.b16 {%0,%1,%2,%3}, [%4];" \
                 : "=r"((r)[0]), "=r"((r)[1]), "=r"((r)[2]), "=r"((r)[3]) \
                 : "r"(addr))

#define STS16(addr, v) \
    asm volatile("st.shared.v4.b32 [%0], {%1,%2,%3,%4};" \
                 :: "r"(addr), "r"((v).x), "r"((v).y), "r"((v).z), "r"((v).w))

DEVFN void mma1688(float* c, const uint32_t* a, uint32_t b0, uint32_t b1) {
    asm volatile(
        "mma.sync.aligned.m16n8k8.row.col.f32.tf32.tf32.f32 "
        "{%0,%1,%2,%3}, {%4,%5,%6,%7}, {%8,%9}, {%0,%1,%2,%3};"
        : "+f"(c[0]), "+f"(c[1]), "+f"(c[2]), "+f"(c[3])
        : "r"(a[0]), "r"(a[1]), "r"(a[2]), "r"(a[3]), "r"(b0), "r"(b1));
}

// ---------------- pre-pass kernels -------------------------------------------
__global__ void k_detect(const int* __restrict__ ids32) {
    if (threadIdx.x == 0) {
        int all0 = 1;
        for (int j = 1; j < 128; j += 2) all0 &= (ids32[j] == 0);
        g_ids64 = all0;
    }
}

DEVFN long long load_id(const void* idsp, int s) {
    return g_ids64 ? ((const long long*)idsp)[s] : (long long)((const int*)idsp)[s];
}

__global__ void k_cvtX(const float4* __restrict__ X4) {
    int i = blockIdx.x * blockDim.x + threadIdx.x;
    float4 v = X4[i];
    ((float4*)g_Xt)[i] = make_float4(totf(v.x), totf(v.y), totf(v.z), totf(v.w));
}

__global__ void k_gatherWh(const float* __restrict__ Wh, const float* __restrict__ bh,
                           const void* __restrict__ idsp) {
    int s = blockIdx.x;
    long long id = load_id(idsp, s);
    const float4* src = (const float4*)(Wh + (size_t)id * DD);
    float4* dst = (float4*)(g_Wgt + (size_t)s * DD);
    for (int j = threadIdx.x; j < DD / 4; j += blockDim.x) {
        float4 v = src[j];
        dst[j] = make_float4(totf(v.x), totf(v.y), totf(v.z), totf(v.w));
    }
    if (threadIdx.x == 0) g_bg[s] = bh[id];
}

__global__ void k_gatherWo(const float* __restrict__ Wo, const void* __restrict__ idsp) {
    int s = blockIdx.x * blockDim.x + threadIdx.x;
    int c = blockIdx.y;
    long long id = load_id(idsp, s);
    g_Wot[(size_t)c * SSZ + s] = totf(Wo[(size_t)c * HH + (size_t)id]);
}

// ---------------- tf32 GEMM via mma.sync -------------------------------------
// C[M,N] = A[M,K]*B[N,K]^T, fp32 data pre-rounded to tf32 (rna). One MMA term.
// CTA tile 128 x TN, BK=16 tf32 (64B rows), SW64 swizzle, double buffer,
// LDG.128 -> register -> STS.128 pipelined fill, 8 warps (4m x 2n),
// ldmatrix.x4.b16 delivers tf32 fragments (tf32 = b16 pair view).
// EPI==0: +bias, relu, tf32-round -> outH fp32. EPI==1: +bias -> outF fp32.

template <int TN, int EPI>
__global__ void __launch_bounds__(256, 2) k_gemm(
    const float* __restrict__ A, const float* __restrict__ B,
    const float* __restrict__ bias,
    float* __restrict__ outF, float* __restrict__ outH,
    int K, int ldo)
{
    constexpr int NJ  = TN / 32;                // x4 B-loads per kstep (n16 each)
    constexpr int NF  = TN / 16;                // n8 accum frags per warp
    constexpr int NCB = TN / 64;                // B 16B-chunks per thread
    constexpr uint32_t ASZ = 128 * 64;          // 8 KB A tile (128 rows x 64B)
    constexpr uint32_t BSZ = (uint32_t)TN * 64;
    constexpr uint32_t STG = ASZ + BSZ;

    extern __shared__ char dsm[];
    __shared__ float s_bias[TN];

    const int tid = threadIdx.x;
    const int wid = tid >> 5, lane = tid & 31;
    const int m0 = blockIdx.y * 128;
    const int n0 = blockIdx.x * TN;
    const uint32_t sbase = (smem_u32(dsm) + 1023u) & ~1023u;

    for (int j = tid; j < TN; j += 256) s_bias[j] = bias[n0 + j];

    // ---- fill descriptors: chunk c -> row c>>2, 16B-word c&3 (coalesced) ----
    uint32_t asoff[2];
    const float* pA[2];
    #pragma unroll
    for (int j = 0; j < 2; j++) {
        int c = tid + j * 256, row = c >> 2, wi = c & 3;
        asoff[j] = SWZ64(row * 64 + wi * 16);
        pA[j] = A + (size_t)(m0 + row) * K + wi * 4;
    }
    uint32_t bsoff[NCB];
    const float* pB[NCB];
    #pragma unroll
    for (int j = 0; j < NCB; j++) {
        int c = tid + j * 256, row = c >> 2, wi = c & 3;
        bsoff[j] = SWZ64(row * 64 + wi * 16);
        pB[j] = B + (size_t)(n0 + row) * K + wi * 4;
    }

    // ---- ldmatrix offsets (loop-invariant, swizzled) ----
    const int wm = wid >> 1, wn = wid & 1;
    const int rA = wm * 32 + (lane & 15);
    const int rB = wn * (TN / 2) + (lane & 15);
    const int kb = (lane >> 4) * 16;
    uint32_t aoff[2][2], boff[NJ][2];
    #pragma unroll
    for (int mi = 0; mi < 2; mi++)
        #pragma unroll
        for (int ks = 0; ks < 2; ks++)
            aoff[mi][ks] = SWZ64((rA + mi * 16) * 64 + ks * 32 + kb);
    #pragma unroll
    for (int nj = 0; nj < NJ; nj++)
        #pragma unroll
        for (int ks = 0; ks < 2; ks++)
            boff[nj][ks] = SWZ64((rB + nj * 16) * 64 + ks * 32 + kb);

    float acc[2][NF][4];
    #pragma unroll
    for (int i = 0; i < 2; i++)
        #pragma unroll
        for (int j = 0; j < NF; j++)
            #pragma unroll
            for (int q = 0; q < 4; q++) acc[i][j][q] = 0.0f;

    uint4 sA[2], sB[NCB];

    auto ldg = [&](int kt) {
        const size_t off = (size_t)kt * 16;     // BK = 16 tf32
        #pragma unroll
        for (int j = 0; j < 2; j++) sA[j] = *(const uint4*)(pA[j] + off);
        #pragma unroll
        for (int j = 0; j < NCB; j++) sB[j] = *(const uint4*)(pB[j] + off);
    };
    auto sts = [&](int b) {
        const uint32_t s0 = sbase + (uint32_t)b * STG;
        #pragma unroll
        for (int j = 0; j < 2; j++) STS16(s0 + asoff[j], sA[j]);
        #pragma unroll
        for (int j = 0; j < NCB; j++) STS16(s0 + ASZ + bsoff[j], sB[j]);
    };

    const int KT = K >> 4;
    ldg(0);
    sts(0);
    __syncthreads();

    for (int kt = 0; kt < KT; kt++) {
        const bool more = (kt + 1 < KT);
        if (more) ldg(kt + 1);                  // LDG overlapped with mma below

        const uint32_t s0 = sbase + (uint32_t)(kt & 1) * STG;
        const uint32_t tA = s0, tB = s0 + ASZ;

        #pragma unroll
        for (int ks = 0; ks < 2; ks++) {        // k8 per kstep
            uint32_t a[2][4];
            #pragma unroll
            for (int mi = 0; mi < 2; mi++) LDM4(a[mi], tA + aoff[mi][ks]);
            #pragma unroll
            for (int nj = 0; nj < NJ; nj++) {
                uint32_t bb[4];                 // r0/r1 = b0 of n8-frag 0/1, r2/r3 = b1
                LDM4(bb, tB + boff[nj][ks]);
                #pragma unroll
                for (int mi = 0; mi < 2; mi++) {
                    #pragma unroll
                    for (int p = 0; p < 2; p++)
                        mma1688(acc[mi][nj * 2 + p], a[mi], bb[p], bb[p + 2]);
                }
            }
        }
        if (more) sts((kt + 1) & 1);
        __syncthreads();
    }

    // ---- epilogue: c0,c1 -> row lane>>2, cols 2(lane&3)+{0,1}; c2,c3 -> +8 ----
    const int er = lane >> 2;
    const int ec = 2 * (lane & 3);
    #pragma unroll
    for (int mi = 0; mi < 2; mi++) {
        const int row = m0 + wm * 32 + mi * 16 + er;
        #pragma unroll
        for (int nf = 0; nf < NF; nf++) {
            const int colL = wn * (TN / 2) + nf * 8 + ec;
            const size_t o0 = (size_t)row * ldo + (size_t)(n0 + colL);
            const size_t o1 = o0 + (size_t)8 * ldo;
            float v0 = acc[mi][nf][0] + s_bias[colL];
            float v1 = acc[mi][nf][1] + s_bias[colL + 1];
            float v2 = acc[mi][nf][2] + s_bias[colL];
            float v3 = acc[mi][nf][3] + s_bias[colL + 1];
            if constexpr (EPI == 0) {
                *(float2*)(outH + o0) =
                    make_float2(totf(fmaxf(v0, 0.0f)), totf(fmaxf(v1, 0.0f)));
                *(float2*)(outH + o1) =
                    make_float2(totf(fmaxf(v2, 0.0f)), totf(fmaxf(v3, 0.0f)));
            } else {
                *(float2*)(outF + o0) = make_float2(v0, v1);
                *(float2*)(outF + o1) = make_float2(v2, v3);
            }
        }
    }
}

// ---------------- launch -----------------------------------------------------
// Fork-join: gatherWo (DRAM-bound, feeds only GEMM2) runs on a side stream
// concurrently with cvtX/gatherWh/GEMM1 (tensor-bound). Standard capture-legal
// event fork/join; stream+events are host objects created once (no device mem).
extern "C" void kernel_launch(void* const* d_in, const int* in_sizes, int n_in,
                              void* d_out, int out_size) {
    const float* X   = (const float*)d_in[0];
    const float* Wh  = (const float*)d_in[1];
    const float* bh  = (const float*)d_in[2];
    const float* Wo  = (const float*)d_in[3];
    const float* bo  = (const float*)d_in[4];
    const void*  ids = d_in[5];
    float* out = (float*)d_out;
    (void)in_sizes; (void)n_in; (void)out_size;

    static cudaStream_t s2 = nullptr;
    static cudaEvent_t evFork = nullptr, evJoin = nullptr;
    if (s2 == nullptr) {
        cudaStreamCreateWithFlags(&s2, cudaStreamNonBlocking);
        cudaEventCreateWithFlags(&evFork, cudaEventDisableTiming);
        cudaEventCreateWithFlags(&evJoin, cudaEventDisableTiming);
    }

    void *pXt, *pWgt, *pbg, *pWot, *ph;
    cudaGetSymbolAddress(&pXt, g_Xt);
    cudaGetSymbolAddress(&pWgt, g_Wgt);
    cudaGetSymbolAddress(&pbg, g_bg);
    cudaGetSymbolAddress(&pWot, g_Wot);
    cudaGetSymbolAddress(&ph, g_h);

    // smem: 2 stages; stage = 8KB (A) + TN*64B (B). +1KB alignment pad.
    const int smem1 = 2 * (8192 + 128 * 64) + 1024;  // 33792
    const int smem2 = 2 * (8192 + 64 * 64) + 1024;   // 25600
    cudaFuncSetAttribute(k_gemm<128, 0>, cudaFuncAttributeMaxDynamicSharedMemorySize, smem1);
    cudaFuncSetAttribute(k_gemm<64, 1>,  cudaFuncAttributeMaxDynamicSharedMemorySize, smem2);

    k_detect<<<1, 32>>>((const int*)ids);

    // Fork: side stream waits for k_detect, then gathers W_out columns.
    cudaEventRecord(evFork, 0);
    cudaStreamWaitEvent(s2, evFork, 0);
    k_gatherWo<<<dim3(SSZ / 256, CC), 256, 0, s2>>>(Wo, ids);
    cudaEventRecord(evJoin, s2);

    // Main branch: GEMM1 prerequisites + GEMM1 (overlaps with gatherWo).
    k_cvtX<<<(NB * DD / 4) / 256, 256>>>((const float4*)X);
    k_gatherWh<<<SSZ, 128>>>(Wh, bh, ids);

    // GEMM1: h = tf32(relu(X * Wg^T + bg)). M=2048, N=8192, K=1024.
    k_gemm<128, 0><<<dim3(SSZ / 128, NB / 128), 256, smem1>>>(
        (const float*)pXt, (const float*)pWgt, (const float*)pbg,
        nullptr, (float*)ph, DD, SSZ);

    // Join: GEMM2 needs both h (main branch) and Wot (side branch).
    cudaStreamWaitEvent(0, evJoin, 0);

    // GEMM2: out = h * WoT^T + b_out (fp32). M=2048, N=1024, K=8192.
    k_gemm<64, 1><<<dim3(CC / 64, NB / 128), 256, smem2>>>(
        (const float*)ph, (const float*)pWot, bo,
        out, nullptr, SSZ, CC);
}

// round 12
// speedup vs baseline: 2.9454x; 1.7806x over previous
#include <cuda_runtime.h>
#include <cuda_fp16.h>
#include <cstdint>

// Problem sizes (fixed).
#define NB  2048
#define DD  1024
#define HH  131072
#define CC  1024
#define SSZ 8192

// ---------------- scratch (device globals; no allocation allowed) -----------
__device__ __half g_Xh[NB * DD];               // X, fp16-rounded
__device__ __half g_Wgh[SSZ * DD];             // gathered W_hidden rows, fp16
__device__ float  g_bg[SSZ];                   // gathered b_hidden (exact fp32)
__device__ __half g_Woh[(size_t)CC * SSZ];     // gathered W_out cols, fp16
__device__ __half g_h[(size_t)NB * SSZ];       // relu hidden, fp16
__device__ int g_ids64;

#define DEVFN __device__ __forceinline__

DEVFN uint32_t smem_u32(const void* p) {
    uint32_t a;
    asm("{ .reg .u64 t; cvta.to.shared.u64 t, %1; cvt.u32.u64 %0, t; }"
        : "=r"(a) : "l"(p));
    return a;
}

DEVFN uint32_t pack2h(__half a, __half b) {
    return (uint32_t)__half_as_ushort(a) | ((uint32_t)__half_as_ushort(b) << 16);
}

// SW64 swizzle for 64-byte rows: XOR 16B-chunk bits [5:4] with row bits [8:7].
#define SWZ64(o) ((uint32_t)(o) ^ ((((uint32_t)(o)) >> 3) & 0x30u))

#define LDM4(r, addr) \
    asm volatile("ldmatrix.sync.aligned.m8n8.x4.shared.b16 {%0,%1,%2,%3}, [%4];" \
                 : "=r"((r)[0]), "=r"((r)[1]), "=r"((r)[2]), "=r"((r)[3]) \
                 : "r"(addr))

#define STS16(addr, v) \
    asm volatile("st.shared.v4.b32 [%0], {%1,%2,%3,%4};" \
                 :: "r"(addr), "r"((v).x), "r"((v).y), "r"((v).z), "r"((v).w))

DEVFN void mma16816(float* c, const uint32_t* a, uint32_t b0, uint32_t b1) {
    asm volatile(
        "mma.sync.aligned.m16n8k16.row.col.f32.f16.f16.f32 "
        "{%0,%1,%2,%3}, {%4,%5,%6,%7}, {%8,%9}, {%0,%1,%2,%3};"
        : "+f"(c[0]), "+f"(c[1]), "+f"(c[2]), "+f"(c[3])
        : "r"(a[0]), "r"(a[1]), "r"(a[2]), "r"(a[3]), "r"(b0), "r"(b1));
}

// ---------------- pre-pass kernels -------------------------------------------
__global__ void k_detect(const int* __restrict__ ids32) {
    if (threadIdx.x == 0) {
        int all0 = 1;
        for (int j = 1; j < 128; j += 2) all0 &= (ids32[j] == 0);
        g_ids64 = all0;
    }
}

DEVFN long long load_id(const void* idsp, int s) {
    return g_ids64 ? ((const long long*)idsp)[s] : (long long)((const int*)idsp)[s];
}

__global__ void k_cvtX(const float4* __restrict__ X4) {
    int i = blockIdx.x * blockDim.x + threadIdx.x;
    float4 v = X4[i];
    ((uint2*)g_Xh)[i] = make_uint2(
        pack2h(__float2half_rn(v.x), __float2half_rn(v.y)),
        pack2h(__float2half_rn(v.z), __float2half_rn(v.w)));
}

__global__ void k_gatherWh(const float* __restrict__ Wh, const float* __restrict__ bh,
                           const void* __restrict__ idsp) {
    int s = blockIdx.x;
    long long id = load_id(idsp, s);
    const float4* src = (const float4*)(Wh + (size_t)id * DD);
    uint2* dst = (uint2*)(g_Wgh + (size_t)s * DD);
    for (int j = threadIdx.x; j < DD / 4; j += blockDim.x) {
        float4 v = src[j];
        dst[j] = make_uint2(
            pack2h(__float2half_rn(v.x), __float2half_rn(v.y)),
            pack2h(__float2half_rn(v.z), __float2half_rn(v.w)));
    }
    if (threadIdx.x == 0) g_bg[s] = bh[id];
}

__global__ void k_gatherWo(const float* __restrict__ Wo, const void* __restrict__ idsp) {
    int s = blockIdx.x * blockDim.x + threadIdx.x;
    int c = blockIdx.y;
    long long id = load_id(idsp, s);
    g_Woh[(size_t)c * SSZ + s] = __float2half_rn(Wo[(size_t)c * HH + (size_t)id]);
}

// ---------------- fp16 GEMM via mma.sync (m16n8k16) --------------------------
// C[M,N] = A[M,K]*B[N,K]^T, fp32 data pre-rounded to fp16 (rn). One MMA term:
// fp16 mantissa (11 bits) == tf32 mantissa, but k16 shape halves instructions.
// CTA tile 128 x TN, BK=32 halfs (64B rows), SW64 swizzle, double buffer,
// LDG.128 -> register -> STS.128 pipelined fill, 8 warps (4m x 2n),
// ldmatrix.x4 both operands (K-major). 2 CTAs/SM.
// EPI==0: +bias, relu -> outH fp16. EPI==1: +bias -> outF fp32.

template <int TN, int EPI>
__global__ void __launch_bounds__(256, 2) k_gemm(
    const __half* __restrict__ A, const __half* __restrict__ B,
    const float* __restrict__ bias,
    float* __restrict__ outF, __half* __restrict__ outH,
    int K, int ldo)
{
    constexpr int NJ  = TN / 32;                // x4 B-loads per kstep (n16 each)
    constexpr int NF  = TN / 16;                // n8 accum frags per warp
    constexpr int NCB = TN / 64;                // B 16B-chunks per thread
    constexpr uint32_t ASZ = 128 * 64;          // 8 KB A tile (128 rows x 64B)
    constexpr uint32_t BSZ = (uint32_t)TN * 64;
    constexpr uint32_t STG = ASZ + BSZ;

    extern __shared__ char dsm[];
    __shared__ float s_bias[TN];

    const int tid = threadIdx.x;
    const int wid = tid >> 5, lane = tid & 31;
    const int m0 = blockIdx.y * 128;
    const int n0 = blockIdx.x * TN;
    const uint32_t sbase = (smem_u32(dsm) + 1023u) & ~1023u;

    for (int j = tid; j < TN; j += 256) s_bias[j] = bias[n0 + j];

    // ---- fill descriptors: chunk c -> row c>>2, 16B-word c&3 (coalesced) ----
    uint32_t asoff[2];
    const __half* pA[2];
    #pragma unroll
    for (int j = 0; j < 2; j++) {
        int c = tid + j * 256, row = c >> 2, wi = c & 3;
        asoff[j] = SWZ64(row * 64 + wi * 16);
        pA[j] = A + (size_t)(m0 + row) * K + wi * 8;
    }
    uint32_t bsoff[NCB];
    const __half* pB[NCB];
    #pragma unroll
    for (int j = 0; j < NCB; j++) {
        int c = tid + j * 256, row = c >> 2, wi = c & 3;
        bsoff[j] = SWZ64(row * 64 + wi * 16);
        pB[j] = B + (size_t)(n0 + row) * K + wi * 8;
    }

    // ---- ldmatrix offsets (loop-invariant, swizzled; same bytes as R7) ----
    const int wm = wid >> 1, wn = wid & 1;
    const int rA = wm * 32 + (lane & 15);
    const int rB = wn * (TN / 2) + (lane & 15);
    const int kb = (lane >> 4) * 16;
    uint32_t aoff[2][2], boff[NJ][2];
    #pragma unroll
    for (int mi = 0; mi < 2; mi++)
        #pragma unroll
        for (int ks = 0; ks < 2; ks++)
            aoff[mi][ks] = SWZ64((rA + mi * 16) * 64 + ks * 32 + kb);
    #pragma unroll
    for (int nj = 0; nj < NJ; nj++)
        #pragma unroll
        for (int ks = 0; ks < 2; ks++)
            boff[nj][ks] = SWZ64((rB + nj * 16) * 64 + ks * 32 + kb);

    float acc[2][NF][4];
    #pragma unroll
    for (int i = 0; i < 2; i++)
        #pragma unroll
        for (int j = 0; j < NF; j++)
            #pragma unroll
            for (int q = 0; q < 4; q++) acc[i][j][q] = 0.0f;

    uint4 sA[2], sB[NCB];

    auto ldg = [&](int kt) {
        const size_t off = (size_t)kt * 32;     // BK = 32 halfs
        #pragma unroll
        for (int j = 0; j < 2; j++) sA[j] = *(const uint4*)(pA[j] + off);
        #pragma unroll
        for (int j = 0; j < NCB; j++) sB[j] = *(const uint4*)(pB[j] + off);
    };
    auto sts = [&](int b) {
        const uint32_t s0 = sbase + (uint32_t)b * STG;
        #pragma unroll
        for (int j = 0; j < 2; j++) STS16(s0 + asoff[j], sA[j]);
        #pragma unroll
        for (int j = 0; j < NCB; j++) STS16(s0 + ASZ + bsoff[j], sB[j]);
    };

    const int KT = K >> 5;
    ldg(0);
    sts(0);
    __syncthreads();

    for (int kt = 0; kt < KT; kt++) {
        const bool more = (kt + 1 < KT);
        if (more) ldg(kt + 1);                  // LDG overlapped with mma below

        const uint32_t s0 = sbase + (uint32_t)(kt & 1) * STG;
        const uint32_t tA = s0, tB = s0 + ASZ;

        #pragma unroll
        for (int ks = 0; ks < 2; ks++) {        // k16 per kstep
            uint32_t a[2][4];
            #pragma unroll
            for (int mi = 0; mi < 2; mi++) LDM4(a[mi], tA + aoff[mi][ks]);
            #pragma unroll
            for (int nj = 0; nj < NJ; nj++) {
                uint32_t bb[4];                 // r0/r1 = b0 of n8-frag 0/1, r2/r3 = b1
                LDM4(bb, tB + boff[nj][ks]);
                #pragma unroll
                for (int mi = 0; mi < 2; mi++) {
                    #pragma unroll
                    for (int p = 0; p < 2; p++)
                        mma16816(acc[mi][nj * 2 + p], a[mi], bb[p], bb[p + 2]);
                }
            }
        }
        if (more) sts((kt + 1) & 1);
        __syncthreads();
    }

    // ---- epilogue: c0,c1 -> row lane>>2, cols 2(lane&3)+{0,1}; c2,c3 -> +8 ----
    const int er = lane >> 2;
    const int ec = 2 * (lane & 3);
    #pragma unroll
    for (int mi = 0; mi < 2; mi++) {
        const int row = m0 + wm * 32 + mi * 16 + er;
        #pragma unroll
        for (int nf = 0; nf < NF; nf++) {
            const int colL = wn * (TN / 2) + nf * 8 + ec;
            const size_t o0 = (size_t)row * ldo + (size_t)(n0 + colL);
            const size_t o1 = o0 + (size_t)8 * ldo;
            float v0 = acc[mi][nf][0] + s_bias[colL];
            float v1 = acc[mi][nf][1] + s_bias[colL + 1];
            float v2 = acc[mi][nf][2] + s_bias[colL];
            float v3 = acc[mi][nf][3] + s_bias[colL + 1];
            if constexpr (EPI == 0) {
                *(uint32_t*)(outH + o0) = pack2h(
                    __float2half_rn(fmaxf(v0, 0.0f)), __float2half_rn(fmaxf(v1, 0.0f)));
                *(uint32_t*)(outH + o1) = pack2h(
                    __float2half_rn(fmaxf(v2, 0.0f)), __float2half_rn(fmaxf(v3, 0.0f)));
            } else {
                *(float2*)(outF + o0) = make_float2(v0, v1);
                *(float2*)(outF + o1) = make_float2(v2, v3);
            }
        }
    }
}

// ---------------- launch -----------------------------------------------------
// Fork-join: gatherWo (DRAM-bound, feeds only GEMM2) runs on a high-priority
// side stream concurrently with the GEMM1 branch. Host objects created once.
extern "C" void kernel_launch(void* const* d_in, const int* in_sizes, int n_in,
                              void* d_out, int out_size) {
    const float* X   = (const float*)d_in[0];
    const float* Wh  = (const float*)d_in[1];
    const float* bh  = (const float*)d_in[2];
    const float* Wo  = (const float*)d_in[3];
    const float* bo  = (const float*)d_in[4];
    const void*  ids = d_in[5];
    float* out = (float*)d_out;
    (void)in_sizes; (void)n_in; (void)out_size;

    static cudaStream_t s2 = nullptr;
    static cudaEvent_t evFork = nullptr, evJoin = nullptr;
    if (s2 == nullptr) {
        int lo, hi;
        cudaDeviceGetStreamPriorityRange(&lo, &hi);
        cudaStreamCreateWithPriority(&s2, cudaStreamNonBlocking, hi);
        cudaEventCreateWithFlags(&evFork, cudaEventDisableTiming);
        cudaEventCreateWithFlags(&evJoin, cudaEventDisableTiming);
    }

    void *pXh, *pWgh, *pbg, *pWoh, *ph;
    cudaGetSymbolAddress(&pXh, g_Xh);
    cudaGetSymbolAddress(&pWgh, g_Wgh);
    cudaGetSymbolAddress(&pbg, g_bg);
    cudaGetSymbolAddress(&pWoh, g_Woh);
    cudaGetSymbolAddress(&ph, g_h);

    // smem: 2 stages; stage = 8KB (A) + TN*64B (B). +1KB alignment pad.
    const int smem1 = 2 * (8192 + 128 * 64) + 1024;  // 33792
    const int smem2 = 2 * (8192 + 64 * 64) + 1024;   // 25600
    cudaFuncSetAttribute(k_gemm<128, 0>, cudaFuncAttributeMaxDynamicSharedMemorySize, smem1);
    cudaFuncSetAttribute(k_gemm<64, 1>,  cudaFuncAttributeMaxDynamicSharedMemorySize, smem2);

    k_detect<<<1, 32>>>((const int*)ids);

    // Fork: side stream waits for k_detect, then gathers W_out columns.
    cudaEventRecord(evFork, 0);
    cudaStreamWaitEvent(s2, evFork, 0);
    k_gatherWo<<<dim3(SSZ / 256, CC), 256, 0, s2>>>(Wo, ids);
    cudaEventRecord(evJoin, s2);

    // Main branch: GEMM1 prerequisites + GEMM1 (overlaps with gatherWo).
    k_cvtX<<<(NB * DD / 4) / 256, 256>>>((const float4*)X);
    k_gatherWh<<<SSZ, 128>>>(Wh, bh, ids);

    // GEMM1: h = fp16(relu(X * Wg^T + bg)). M=2048, N=8192, K=1024.
    k_gemm<128, 0><<<dim3(SSZ / 128, NB / 128), 256, smem1>>>(
        (const __half*)pXh, (const __half*)pWgh, (const float*)pbg,
        nullptr, (__half*)ph, DD, SSZ);

    // Join: GEMM2 needs both h (main branch) and Woh (side branch).
    cudaStreamWaitEvent(0, evJoin, 0);

    // GEMM2: out = h * WoT^T + b_out (fp32). M=2048, N=1024, K=8192.
    k_gemm<64, 1><<<dim3(CC / 64, NB / 128), 256, smem2>>>(
        (const __half*)ph, (const __half*)pWoh, bo,
        out, nullptr, SSZ, CC);
}